// round 11
// baseline (speedup 1.0000x reference)
#include <cuda_runtime.h>
#include <cuda_fp16.h>
#include <stdint.h>

// rgb[n,d] = (1/Z_n) * sum_e enc[n,e] * D[n, d*72+e]
// D = A @ W',  A[n,c] = exp2(s'_nc - ub_n),  s' = x[:3].(centroid*log2e),
// ub_n = |x[:3]| * max_c |centroid'_c|
// Pipelined: softmax/pack(t+1) overlaps GEMM(t).
// 16 warps = 2 m-groups (64 rows) x 4 k-quarters (64) x 2 n-halves.
// Register-disciplined rework of the m2k4n2 partition (R10 spilled).

constexpr int TPB    = 512;
constexpr int TILE_M = 128;
constexpr int NC     = 256;
constexpr int EDIM   = 72;
constexpr int NOUT   = 216;

constexpr int ROW_B  = 528;            // A/W' smem row bytes (132 words)
constexpr int ENC_B  = 544;            // bytes per enc e-pair row
constexpr int ENC_BUF = 36 * ENC_B;    // 19584

constexpr int OFF_CENT = 0;                          // 4096
constexpr int OFF_MRED = 4096;                       // 64
constexpr int OFF_WP   = 4160;                       // 216*528 = 114048
constexpr int OFF_A    = OFF_WP + NOUT * ROW_B;      // 118208
constexpr int OFF_ENC  = OFF_A + TILE_M * ROW_B;     // 185792 (x2)
constexpr int OFF_INVZ = OFF_ENC + 2 * ENC_BUF;      // 224960 (2*128 floats)
constexpr int OFF_RACC = OFF_INVZ + 1024;            // 225984 (2*512 floats)
constexpr int SMEM_BYTES = OFF_RACC + 4096;          // 230080

constexpr float LOG2E = 1.4426950408889634f;

__device__ __forceinline__ uint32_t s2u(const void* p) {
    uint32_t a;
    asm("{ .reg .u64 t; cvta.to.shared.u64 t, %1; cvt.u32.u64 %0, t; }"
        : "=r"(a) : "l"(p));
    return a;
}
__device__ __forceinline__ void ldsm4(uint32_t* r, uint32_t addr) {
    asm volatile("ldmatrix.sync.aligned.m8n8.x4.shared.b16 {%0,%1,%2,%3}, [%4];"
                 : "=r"(r[0]), "=r"(r[1]), "=r"(r[2]), "=r"(r[3]) : "r"(addr));
}
__device__ __forceinline__ void ldsm2(uint32_t* r, uint32_t addr) {
    asm volatile("ldmatrix.sync.aligned.m8n8.x2.shared.b16 {%0,%1}, [%2];"
                 : "=r"(r[0]), "=r"(r[1]) : "r"(addr));
}
__device__ __forceinline__ void lds128(uint32_t& r0, uint32_t& r1,
                                       uint32_t& r2, uint32_t& r3, uint32_t addr) {
    asm volatile("ld.shared.v4.b32 {%0,%1,%2,%3}, [%4];"
                 : "=r"(r0), "=r"(r1), "=r"(r2), "=r"(r3) : "r"(addr));
}
__device__ __forceinline__ void hmma(float& d0, float& d1, float& d2, float& d3,
                                     const uint32_t* a, const uint32_t* b) {
    asm volatile("mma.sync.aligned.m16n8k16.row.col.f32.f16.f16.f32 "
                 "{%0,%1,%2,%3}, {%4,%5,%6,%7}, {%8,%9}, {%0,%1,%2,%3};"
                 : "+f"(d0), "+f"(d1), "+f"(d2), "+f"(d3)
                 : "r"(a[0]), "r"(a[1]), "r"(a[2]), "r"(a[3]), "r"(b[0]), "r"(b[1]));
}
__device__ __forceinline__ void fold2(float& acc, float d0, float d1, uint32_t h2raw) {
    __half2 h = *reinterpret_cast<__half2*>(&h2raw);
    float2 e = __half22float2(h);
    acc = fmaf(d0, e.x, fmaf(d1, e.y, acc));
}

// One 8-col strip: 4 ldsm2 B frags, 16 HMMAs done as two m-tile pairs
// (d[8] live instead of 16), 2 bulk LDS.128 enc folds for the 8 row-groups.
template<int SL>
__device__ __forceinline__ void gemm_strip(
    uint32_t bstrip, const uint32_t (&a)[4][4][4], int eo,
    uint32_t eb, float (&acc)[8][2])
{
    uint32_t b[4][2];
#pragma unroll
    for (int kk = 0; kk < 4; ++kk) ldsm2(b[kk], bstrip + kk * 32);

    const uint32_t ea = eb + (uint32_t)(eo >> 1) * ENC_B;
    uint32_t r0, r1, r2, r3;
    float d[8];

    // m-tile pair 0 (rows 0..31 of the warp's 64)
#pragma unroll
    for (int i = 0; i < 8; ++i) d[i] = 0.f;
#pragma unroll
    for (int kk = 0; kk < 4; ++kk) {
        hmma(d[0], d[1], d[2], d[3], a[0][kk], b[kk]);
        hmma(d[4], d[5], d[6], d[7], a[1][kk], b[kk]);
    }
    lds128(r0, r1, r2, r3, ea);
    fold2(acc[0][SL], d[0], d[1], r0);
    fold2(acc[1][SL], d[2], d[3], r1);
    fold2(acc[2][SL], d[4], d[5], r2);
    fold2(acc[3][SL], d[6], d[7], r3);

    // m-tile pair 1 (rows 32..63)
#pragma unroll
    for (int i = 0; i < 8; ++i) d[i] = 0.f;
#pragma unroll
    for (int kk = 0; kk < 4; ++kk) {
        hmma(d[0], d[1], d[2], d[3], a[2][kk], b[kk]);
        hmma(d[4], d[5], d[6], d[7], a[3][kk], b[kk]);
    }
    lds128(r0, r1, r2, r3, ea + 128);
    fold2(acc[4][SL], d[0], d[1], r0);
    fold2(acc[5][SL], d[2], d[3], r1);
    fold2(acc[6][SL], d[4], d[5], r2);
    fold2(acc[7][SL], d[6], d[7], r3);
}

__device__ __forceinline__ void load_afrags(uint32_t (&a)[4][4][4],
                                            uint32_t sb, int mw, int kh, int l)
{
    const uint32_t a_base = sb + OFF_A
        + (uint32_t)((mw * 64 + (l & 15)) * ROW_B + kh * 128 + (l >> 4) * 16);
#pragma unroll
    for (int mt = 0; mt < 4; ++mt)
#pragma unroll
        for (int kk = 0; kk < 4; ++kk)
            ldsm4(a[mt][kk], a_base + mt * 16 * ROW_B + kk * 32);
}

// Register-lean softmax + streaming enc + A-pack.
__device__ __forceinline__ void softmax_pack(
    const float* __restrict__ X, const float4* __restrict__ c4,
    __half2* __restrict__ atp, __half2* __restrict__ encp,
    float* __restrict__ invZp, float Mn,
    int t, int N, int pt, int q, int gp)
{
    const int p = t * TILE_M + pt;
    float x0 = 0.f, x1 = 0.f, x2 = 0.f;
    if (p < N) { x0 = X[p * 6 + 0]; x1 = X[p * 6 + 1]; x2 = X[p * 6 + 2]; }

    if (q < 3) {
#pragma unroll
        for (int dd = 0; dd < 2; ++dd) {
            const int d = 2 * q + dd;
            float xv = (p < N) ? X[p * 6 + d] : 0.f;
            float s, c;
            __sincosf(xv, &s, &c);
#pragma unroll
            for (int tt = 0; tt < 3; ++tt) {
                // pair (freq 2tt, 2tt+1): advance once, store both, advance again
                float s1 = 2.f * s * c;
                float c1 = fmaf(-2.f * s, s, 1.f);
                encp[(d * 6 + tt) * (ENC_B / 4) + gp]     = __floats2half2_rn(s, s1);
                encp[(d * 6 + 3 + tt) * (ENC_B / 4) + gp] = __floats2half2_rn(c, c1);
                s = 2.f * s1 * c1;
                c = fmaf(-2.f * s1, s1, 1.f);
            }
        }
    }

    const float ub = sqrtf(fmaf(x0, x0, fmaf(x1, x1, x2 * x2))) * Mn;
    const float4* cb = c4 + (q << 6);
    float z = 0.f;
#pragma unroll 4
    for (int j = 0; j < 64; j += 2) {
        const int u0 = (j + 2 * q) & 63;
        float4 ca = cb[u0], cd = cb[u0 + 1];
        float s0 = fmaf(x0, ca.x, fmaf(x1, ca.y, x2 * ca.z)) - ub;
        float s1 = fmaf(x0, cd.x, fmaf(x1, cd.y, x2 * cd.z)) - ub;
        float w0, w1;
        asm("ex2.approx.ftz.f32 %0, %1;" : "=f"(w0) : "f"(s0));
        asm("ex2.approx.ftz.f32 %0, %1;" : "=f"(w1) : "f"(s1));
        __half2 h2 = __floats2half2_rn(w0, w1);
        z += __low2float(h2) + __high2float(h2);
        atp[pt * 132 + (((q << 6) + u0) >> 1)] = h2;
    }
    z += __shfl_xor_sync(0xffffffffu, z, 1);
    z += __shfl_xor_sync(0xffffffffu, z, 2);
    if (q == 0) invZp[pt] = __frcp_rn(z);
}

__global__ __launch_bounds__(TPB, 1)
void rgb_hmma_kernel(const float* __restrict__ X,
                     const float* __restrict__ W,
                     const float* __restrict__ cent,
                     float* __restrict__ out, int N, int n_tiles)
{
    extern __shared__ char smem[];
    const uint32_t sb = s2u(smem);
    float4*  c4   = reinterpret_cast<float4*>(smem + OFF_CENT);
    float*   mred = reinterpret_cast<float*>(smem + OFF_MRED);
    __half*  wp   = reinterpret_cast<__half*>(smem + OFF_WP);
    __half2* atp  = reinterpret_cast<__half2*>(smem + OFF_A);
    float*   invZ = reinterpret_cast<float*>(smem + OFF_INVZ);
    float*   racc = reinterpret_cast<float*>(smem + OFF_RACC);

    const int tid = threadIdx.x;
    const int w = tid >> 5, l = tid & 31;

    for (int i = tid; i < NC; i += TPB) {
        float4 qv;
        qv.x = cent[i * 3 + 0] * LOG2E;
        qv.y = cent[i * 3 + 1] * LOG2E;
        qv.z = cent[i * 3 + 2] * LOG2E;
        qv.w = 0.f;
        c4[i] = qv;
    }
    for (int i = tid; i < 768 * EDIM; i += TPB) {
        int r = i / EDIM, e = i - r * EDIM;
        int c = r / 3, d = r - 3 * c;
        wp[(d * EDIM + e) * (ROW_B / 2) + c] = __float2half_rn(W[i]);
    }
    racc[tid] = 0.f;
    racc[tid + 512] = 0.f;
    __syncthreads();

    float mn2 = 0.f;
    if (tid < NC) {
        float4 cc = c4[tid];
        mn2 = fmaf(cc.x, cc.x, fmaf(cc.y, cc.y, cc.z * cc.z));
    }
#pragma unroll
    for (int o = 16; o > 0; o >>= 1)
        mn2 = fmaxf(mn2, __shfl_xor_sync(0xffffffffu, mn2, o));
    if (l == 0) mred[w] = mn2;
    __syncthreads();
    float M2 = mred[0];
#pragma unroll
    for (int i = 1; i < 16; ++i) M2 = fmaxf(M2, mred[i]);
    const float Mn = sqrtf(M2);

    const int pt = tid >> 2;
    const int q  = tid & 3;
    const int gp = (pt >> 5) * 32 + (pt & 7) * 4 + ((pt >> 3) & 3);
    const int mw = w & 1, kh = (w >> 1) & 3, nh = w >> 3;
    const int lq = l >> 2;
    const int G = gridDim.x;

    const uint32_t bl2 = sb + OFF_WP
        + (uint32_t)((l & 7) * ROW_B + ((l >> 3) & 1) * 16 + kh * 128);
    const uint32_t eb0 = sb + OFF_ENC
        + (uint32_t)((l & 3) * ENC_B + mw * 256 + lq * 16);

    int t = blockIdx.x;
    int par = 0;
    uint32_t a[4][4][4];
    if (t < n_tiles)
        softmax_pack(X, c4, atp,
                     reinterpret_cast<__half2*>(smem + OFF_ENC),
                     invZ, Mn, t, N, pt, q, gp);
    __syncthreads();
    if (t < n_tiles) load_afrags(a, sb, mw, kh, l);
    __syncthreads();

    for (; t < n_tiles; t += G) {
        const int tn = t + G;
        const int parn = par ^ 1;

        if (tn < n_tiles)
            softmax_pack(X, c4, atp,
                         reinterpret_cast<__half2*>(smem + OFF_ENC + parn * ENC_BUF),
                         invZ + parn * TILE_M, Mn, tn, N, pt, q, gp);

        const uint32_t eb = eb0 + (uint32_t)par * ENC_BUF;
        float acc[8][2];
#pragma unroll
        for (int g = 0; g < 8; ++g) { acc[g][0] = 0.f; acc[g][1] = 0.f; }

        if (nh == 0) {   // strips 0..8 -> dch0 (SL0), 9..13 -> dch1 (SL1)
#pragma unroll
            for (int s = 0; s < 9; ++s)
                gemm_strip<0>(bl2 + (uint32_t)(s * 8 * ROW_B), a, s * 8, eb, acc);
#pragma unroll
            for (int s = 9; s < 14; ++s)
                gemm_strip<1>(bl2 + (uint32_t)(s * 8 * ROW_B), a, s * 8 - 72, eb, acc);
        } else {         // strips 14..17 -> dch1 (SL0), 18..26 -> dch2 (SL1)
#pragma unroll
            for (int s = 14; s < 18; ++s)
                gemm_strip<0>(bl2 + (uint32_t)(s * 8 * ROW_B), a, s * 8 - 72, eb, acc);
#pragma unroll
            for (int s = 18; s < 27; ++s)
                gemm_strip<1>(bl2 + (uint32_t)(s * 8 * ROW_B), a, s * 8 - 144, eb, acc);
        }

        float* raccp = racc + par * 512;
#pragma unroll
        for (int g = 0; g < 8; ++g)
#pragma unroll
            for (int sl = 0; sl < 2; ++sl) {
                float v = acc[g][sl];
                v += __shfl_xor_sync(0xffffffffu, v, 1);
                v += __shfl_xor_sync(0xffffffffu, v, 2);
                if ((l & 3) == 0)
                    atomicAdd(&raccp[(mw * 64 + g * 8 + lq) * 4 + nh + sl], v);
            }
        __syncthreads();   // sync1: pack(t+1) & atomics(t) complete

        if (tn < n_tiles) load_afrags(a, sb, mw, kh, l);

        if (tid < TILE_M) {
            float* rp = racc + par * 512 + tid * 4;
            const int po2 = t * TILE_M + tid;
            if (po2 < N) {
                const float iz = invZ[par * TILE_M + tid];
                out[po2 * 3 + 0] = rp[0] * iz;
                out[po2 * 3 + 1] = rp[1] * iz;
                out[po2 * 3 + 2] = rp[2] * iz;
            }
            rp[0] = 0.f; rp[1] = 0.f; rp[2] = 0.f; rp[3] = 0.f;
        }
        __syncthreads();   // sync2: a-frags(t+1) loaded, racc recycled

        par = parn;
    }
}

extern "C" void kernel_launch(void* const* d_in, const int* in_sizes, int n_in,
                              void* d_out, int out_size)
{
    const float* X    = (const float*)d_in[0];  // [N, 6]
    const float* W    = (const float*)d_in[1];  // [768, 72]
    const float* cent = (const float*)d_in[2];  // [256, 3]
    float* out = (float*)d_out;                 // [N, 3]

    const int N = in_sizes[0] / 6;
    const int n_tiles = (N + TILE_M - 1) / TILE_M;

    int dev = 0, sms = 148;
    cudaGetDevice(&dev);
    cudaDeviceGetAttribute(&sms, cudaDevAttrMultiProcessorCount, dev);

    cudaFuncSetAttribute(rgb_hmma_kernel,
                         cudaFuncAttributeMaxDynamicSharedMemorySize, SMEM_BYTES);

    const int grid = n_tiles < sms ? n_tiles : sms;
    rgb_hmma_kernel<<<grid, TPB, SMEM_BYTES>>>(X, W, cent, out, N, n_tiles);
}

// round 12
// speedup vs baseline: 1.4706x; 1.4706x over previous
#include <cuda_runtime.h>
#include <cuda_fp16.h>
#include <stdint.h>

// rgb[n,d] = (1/Z_n) * sum_e enc[n,e] * D[n, d*72+e]
// D = A @ W',  A[n,c] = exp2(s'_nc - ub_n),  s' = x[:3].(centroid*log2e),
// ub_n = |x[:3]| * max_c |centroid'_c|
// Pipelined: softmax/pack(t+1) overlaps GEMM(t).
// 16 warps = 2 m-groups (64 rows) x 4 k-quarters (64) x 2 n-halves.
// Phase-long accumulators reduced to 8 via per-d-channel flushes (fixes R10/R11 spill).

constexpr int TPB    = 512;
constexpr int TILE_M = 128;
constexpr int NC     = 256;
constexpr int EDIM   = 72;
constexpr int NOUT   = 216;

constexpr int ROW_B  = 528;            // A/W' smem row bytes (132 words)
constexpr int ENC_B  = 544;            // bytes per enc e-pair row
constexpr int ENC_BUF = 36 * ENC_B;    // 19584

constexpr int OFF_CENT = 0;                          // 4096
constexpr int OFF_MRED = 4096;                       // 64
constexpr int OFF_WP   = 4160;                       // 216*528 = 114048
constexpr int OFF_A    = OFF_WP + NOUT * ROW_B;      // 118208
constexpr int OFF_ENC  = OFF_A + TILE_M * ROW_B;     // 185792 (x2)
constexpr int OFF_INVZ = OFF_ENC + 2 * ENC_BUF;      // 224960 (2*128 floats)
constexpr int OFF_RACC = OFF_INVZ + 1024;            // 225984 (2*512 floats)
constexpr int SMEM_BYTES = OFF_RACC + 4096;          // 230080

constexpr float LOG2E = 1.4426950408889634f;

__device__ __forceinline__ uint32_t s2u(const void* p) {
    uint32_t a;
    asm("{ .reg .u64 t; cvta.to.shared.u64 t, %1; cvt.u32.u64 %0, t; }"
        : "=r"(a) : "l"(p));
    return a;
}
__device__ __forceinline__ void ldsm4(uint32_t* r, uint32_t addr) {
    asm volatile("ldmatrix.sync.aligned.m8n8.x4.shared.b16 {%0,%1,%2,%3}, [%4];"
                 : "=r"(r[0]), "=r"(r[1]), "=r"(r[2]), "=r"(r[3]) : "r"(addr));
}
__device__ __forceinline__ void ldsm2(uint32_t* r, uint32_t addr) {
    asm volatile("ldmatrix.sync.aligned.m8n8.x2.shared.b16 {%0,%1}, [%2];"
                 : "=r"(r[0]), "=r"(r[1]) : "r"(addr));
}
__device__ __forceinline__ void lds128(uint32_t& r0, uint32_t& r1,
                                       uint32_t& r2, uint32_t& r3, uint32_t addr) {
    asm volatile("ld.shared.v4.b32 {%0,%1,%2,%3}, [%4];"
                 : "=r"(r0), "=r"(r1), "=r"(r2), "=r"(r3) : "r"(addr));
}
__device__ __forceinline__ void hmma(float& d0, float& d1, float& d2, float& d3,
                                     const uint32_t* a, const uint32_t* b) {
    asm volatile("mma.sync.aligned.m16n8k16.row.col.f32.f16.f16.f32 "
                 "{%0,%1,%2,%3}, {%4,%5,%6,%7}, {%8,%9}, {%0,%1,%2,%3};"
                 : "+f"(d0), "+f"(d1), "+f"(d2), "+f"(d3)
                 : "r"(a[0]), "r"(a[1]), "r"(a[2]), "r"(a[3]), "r"(b[0]), "r"(b[1]));
}
__device__ __forceinline__ void fold2(float& acc, float d0, float d1, uint32_t h2raw) {
    __half2 h = *reinterpret_cast<__half2*>(&h2raw);
    float2 e = __half22float2(h);
    acc = fmaf(d0, e.x, fmaf(d1, e.y, acc));
}

// One 8-col strip: 4 ldsm2 B frags, 16 HMMAs as two m-tile pairs (d[8] live),
// 2 bulk LDS.128 enc folds for the warp's 8 row-groups. Single-slot acc[8].
__device__ __forceinline__ void gemm_strip(
    uint32_t bstrip, const uint32_t (&a)[4][4][4], int eo,
    uint32_t eb, float (&acc)[8])
{
    uint32_t b[4][2];
#pragma unroll
    for (int kk = 0; kk < 4; ++kk) ldsm2(b[kk], bstrip + kk * 32);

    const uint32_t ea = eb + (uint32_t)(eo >> 1) * ENC_B;
    uint32_t r0, r1, r2, r3;
    float d[8];

    // m-tile pair 0 (warp rows 0..31)
#pragma unroll
    for (int i = 0; i < 8; ++i) d[i] = 0.f;
#pragma unroll
    for (int kk = 0; kk < 4; ++kk) {
        hmma(d[0], d[1], d[2], d[3], a[0][kk], b[kk]);
        hmma(d[4], d[5], d[6], d[7], a[1][kk], b[kk]);
    }
    lds128(r0, r1, r2, r3, ea);
    fold2(acc[0], d[0], d[1], r0);
    fold2(acc[1], d[2], d[3], r1);
    fold2(acc[2], d[4], d[5], r2);
    fold2(acc[3], d[6], d[7], r3);

    // m-tile pair 1 (warp rows 32..63)
#pragma unroll
    for (int i = 0; i < 8; ++i) d[i] = 0.f;
#pragma unroll
    for (int kk = 0; kk < 4; ++kk) {
        hmma(d[0], d[1], d[2], d[3], a[2][kk], b[kk]);
        hmma(d[4], d[5], d[6], d[7], a[3][kk], b[kk]);
    }
    lds128(r0, r1, r2, r3, ea + 128);
    fold2(acc[4], d[0], d[1], r0);
    fold2(acc[5], d[2], d[3], r1);
    fold2(acc[6], d[4], d[5], r2);
    fold2(acc[7], d[6], d[7], r3);
}

// Reduce acc[8] across the lane-quad, atomicAdd into racc column `col`, zero acc.
__device__ __forceinline__ void flush_acc(float (&acc)[8], float* raccp,
                                          int mw, int lq, int l, int col)
{
#pragma unroll
    for (int g = 0; g < 8; ++g) {
        float v = acc[g];
        v += __shfl_xor_sync(0xffffffffu, v, 1);
        v += __shfl_xor_sync(0xffffffffu, v, 2);
        if ((l & 3) == 0)
            atomicAdd(&raccp[(mw * 64 + g * 8 + lq) * 4 + col], v);
        acc[g] = 0.f;
    }
}

__device__ __forceinline__ void load_afrags(uint32_t (&a)[4][4][4],
                                            uint32_t sb, int mw, int kh, int l)
{
    const uint32_t a_base = sb + OFF_A
        + (uint32_t)((mw * 64 + (l & 15)) * ROW_B + kh * 128 + (l >> 4) * 16);
#pragma unroll
    for (int mt = 0; mt < 4; ++mt)
#pragma unroll
        for (int kk = 0; kk < 4; ++kk)
            ldsm4(a[mt][kk], a_base + mt * 16 * ROW_B + kk * 32);
}

// Register-lean softmax + streaming enc + A-pack.
__device__ __forceinline__ void softmax_pack(
    const float* __restrict__ X, const float4* __restrict__ c4,
    __half2* __restrict__ atp, __half2* __restrict__ encp,
    float* __restrict__ invZp, float Mn,
    int t, int N, int pt, int q, int gp)
{
    const int p = t * TILE_M + pt;
    float x0 = 0.f, x1 = 0.f, x2 = 0.f;
    if (p < N) { x0 = X[p * 6 + 0]; x1 = X[p * 6 + 1]; x2 = X[p * 6 + 2]; }

    if (q < 3) {
#pragma unroll
        for (int dd = 0; dd < 2; ++dd) {
            const int d = 2 * q + dd;
            float xv = (p < N) ? X[p * 6 + d] : 0.f;
            float s, c;
            __sincosf(xv, &s, &c);
#pragma unroll
            for (int tt = 0; tt < 3; ++tt) {
                float s1 = 2.f * s * c;
                float c1 = fmaf(-2.f * s, s, 1.f);
                encp[(d * 6 + tt) * (ENC_B / 4) + gp]     = __floats2half2_rn(s, s1);
                encp[(d * 6 + 3 + tt) * (ENC_B / 4) + gp] = __floats2half2_rn(c, c1);
                s = 2.f * s1 * c1;
                c = fmaf(-2.f * s1, s1, 1.f);
            }
        }
    }

    const float ub = sqrtf(fmaf(x0, x0, fmaf(x1, x1, x2 * x2))) * Mn;
    const float4* cb = c4 + (q << 6);
    float z = 0.f;
#pragma unroll 4
    for (int j = 0; j < 64; j += 2) {
        const int u0 = (j + 2 * q) & 63;
        float4 ca = cb[u0], cd = cb[u0 + 1];
        float s0 = fmaf(x0, ca.x, fmaf(x1, ca.y, x2 * ca.z)) - ub;
        float s1 = fmaf(x0, cd.x, fmaf(x1, cd.y, x2 * cd.z)) - ub;
        float w0, w1;
        asm("ex2.approx.ftz.f32 %0, %1;" : "=f"(w0) : "f"(s0));
        asm("ex2.approx.ftz.f32 %0, %1;" : "=f"(w1) : "f"(s1));
        __half2 h2 = __floats2half2_rn(w0, w1);
        z += __low2float(h2) + __high2float(h2);
        atp[pt * 132 + (((q << 6) + u0) >> 1)] = h2;
    }
    z += __shfl_xor_sync(0xffffffffu, z, 1);
    z += __shfl_xor_sync(0xffffffffu, z, 2);
    if (q == 0) invZp[pt] = __frcp_rn(z);
}

__global__ __launch_bounds__(TPB, 1)
void rgb_hmma_kernel(const float* __restrict__ X,
                     const float* __restrict__ W,
                     const float* __restrict__ cent,
                     float* __restrict__ out, int N, int n_tiles)
{
    extern __shared__ char smem[];
    const uint32_t sb = s2u(smem);
    float4*  c4   = reinterpret_cast<float4*>(smem + OFF_CENT);
    float*   mred = reinterpret_cast<float*>(smem + OFF_MRED);
    __half*  wp   = reinterpret_cast<__half*>(smem + OFF_WP);
    __half2* atp  = reinterpret_cast<__half2*>(smem + OFF_A);
    float*   invZ = reinterpret_cast<float*>(smem + OFF_INVZ);
    float*   racc = reinterpret_cast<float*>(smem + OFF_RACC);

    const int tid = threadIdx.x;
    const int w = tid >> 5, l = tid & 31;

    for (int i = tid; i < NC; i += TPB) {
        float4 qv;
        qv.x = cent[i * 3 + 0] * LOG2E;
        qv.y = cent[i * 3 + 1] * LOG2E;
        qv.z = cent[i * 3 + 2] * LOG2E;
        qv.w = 0.f;
        c4[i] = qv;
    }
    for (int i = tid; i < 768 * EDIM; i += TPB) {
        int r = i / EDIM, e = i - r * EDIM;
        int c = r / 3, d = r - 3 * c;
        wp[(d * EDIM + e) * (ROW_B / 2) + c] = __float2half_rn(W[i]);
    }
    racc[tid] = 0.f;
    racc[tid + 512] = 0.f;
    __syncthreads();

    float mn2 = 0.f;
    if (tid < NC) {
        float4 cc = c4[tid];
        mn2 = fmaf(cc.x, cc.x, fmaf(cc.y, cc.y, cc.z * cc.z));
    }
#pragma unroll
    for (int o = 16; o > 0; o >>= 1)
        mn2 = fmaxf(mn2, __shfl_xor_sync(0xffffffffu, mn2, o));
    if (l == 0) mred[w] = mn2;
    __syncthreads();
    float M2 = mred[0];
#pragma unroll
    for (int i = 1; i < 16; ++i) M2 = fmaxf(M2, mred[i]);
    const float Mn = sqrtf(M2);

    const int pt = tid >> 2;
    const int q  = tid & 3;
    const int gp = (pt >> 5) * 32 + (pt & 7) * 4 + ((pt >> 3) & 3);
    const int mw = w & 1, kh = (w >> 1) & 3, nh = w >> 3;
    const int lq = l >> 2;
    const int G = gridDim.x;

    const uint32_t bl2 = sb + OFF_WP
        + (uint32_t)((l & 7) * ROW_B + ((l >> 3) & 1) * 16 + kh * 128);
    const uint32_t eb0 = sb + OFF_ENC
        + (uint32_t)((l & 3) * ENC_B + mw * 256 + lq * 16);

    int t = blockIdx.x;
    int par = 0;
    uint32_t a[4][4][4];
    if (t < n_tiles)
        softmax_pack(X, c4, atp,
                     reinterpret_cast<__half2*>(smem + OFF_ENC),
                     invZ, Mn, t, N, pt, q, gp);
    __syncthreads();
    if (t < n_tiles) load_afrags(a, sb, mw, kh, l);
    __syncthreads();

    for (; t < n_tiles; t += G) {
        const int tn = t + G;
        const int parn = par ^ 1;

        if (tn < n_tiles)
            softmax_pack(X, c4, atp,
                         reinterpret_cast<__half2*>(smem + OFF_ENC + parn * ENC_BUF),
                         invZ + parn * TILE_M, Mn, tn, N, pt, q, gp);

        const uint32_t eb = eb0 + (uint32_t)par * ENC_BUF;
        float* raccp = racc + par * 512;
        float acc[8];
#pragma unroll
        for (int g = 0; g < 8; ++g) acc[g] = 0.f;

        if (nh == 0) {   // strips 0..8 -> dch0 (flush col 0), 9..13 -> dch1 (col 1)
#pragma unroll
            for (int s = 0; s < 9; ++s)
                gemm_strip(bl2 + (uint32_t)(s * 8 * ROW_B), a, s * 8, eb, acc);
            flush_acc(acc, raccp, mw, lq, l, 0);
#pragma unroll
            for (int s = 9; s < 14; ++s)
                gemm_strip(bl2 + (uint32_t)(s * 8 * ROW_B), a, s * 8 - 72, eb, acc);
            flush_acc(acc, raccp, mw, lq, l, 1);
        } else {         // strips 14..17 -> dch1 (col 1), 18..26 -> dch2 (col 2)
#pragma unroll
            for (int s = 14; s < 18; ++s)
                gemm_strip(bl2 + (uint32_t)(s * 8 * ROW_B), a, s * 8 - 72, eb, acc);
            flush_acc(acc, raccp, mw, lq, l, 1);
#pragma unroll
            for (int s = 18; s < 27; ++s)
                gemm_strip(bl2 + (uint32_t)(s * 8 * ROW_B), a, s * 8 - 144, eb, acc);
            flush_acc(acc, raccp, mw, lq, l, 2);
        }
        __syncthreads();   // sync1: pack(t+1) & atomics(t) complete

        if (tn < n_tiles) load_afrags(a, sb, mw, kh, l);

        if (tid < TILE_M) {
            float* rp = racc + par * 512 + tid * 4;
            const int po2 = t * TILE_M + tid;
            if (po2 < N) {
                const float iz = invZ[par * TILE_M + tid];
                out[po2 * 3 + 0] = rp[0] * iz;
                out[po2 * 3 + 1] = rp[1] * iz;
                out[po2 * 3 + 2] = rp[2] * iz;
            }
            rp[0] = 0.f; rp[1] = 0.f; rp[2] = 0.f; rp[3] = 0.f;
        }
        __syncthreads();   // sync2: a-frags(t+1) loaded, racc recycled

        par = parn;
    }
}

extern "C" void kernel_launch(void* const* d_in, const int* in_sizes, int n_in,
                              void* d_out, int out_size)
{
    const float* X    = (const float*)d_in[0];  // [N, 6]
    const float* W    = (const float*)d_in[1];  // [768, 72]
    const float* cent = (const float*)d_in[2];  // [256, 3]
    float* out = (float*)d_out;                 // [N, 3]

    const int N = in_sizes[0] / 6;
    const int n_tiles = (N + TILE_M - 1) / TILE_M;

    int dev = 0, sms = 148;
    cudaGetDevice(&dev);
    cudaDeviceGetAttribute(&sms, cudaDevAttrMultiProcessorCount, dev);

    cudaFuncSetAttribute(rgb_hmma_kernel,
                         cudaFuncAttributeMaxDynamicSharedMemorySize, SMEM_BYTES);

    const int grid = n_tiles < sms ? n_tiles : sms;
    rgb_hmma_kernel<<<grid, TPB, SMEM_BYTES>>>(X, W, cent, out, N, n_tiles);
}

// round 13
// speedup vs baseline: 1.6361x; 1.1126x over previous
#include <cuda_runtime.h>
#include <cuda_fp16.h>
#include <stdint.h>

// rgb[n,d] = (1/Z_n) * sum_e enc[n,e] * D[n, d*72+e]
// D = A @ W',  A[n,c] = exp2(s'_nc - ub_n),  s' = x[:3].(centroid*log2e),
// ub_n = |x[:3]| * max_c |centroid'_c|
// WARP-SPECIALIZED: warps 8-15 produce (softmax/enc/pack tile t+1, out tile t-1),
// warps 0-7 consume (HMMA GEMM tile t). Handoff via named barriers.
// Consumers: 2 m-halves (64 rows) x 4 k-quarters (64), full n (27 strips = 3 d-channels).

constexpr int TPB    = 512;
constexpr int TILE_M = 128;
constexpr int NC     = 256;
constexpr int EDIM   = 72;
constexpr int NOUT   = 216;

constexpr int ROW_B  = 528;            // A/W' smem row bytes (132 words)
constexpr int ENC_B  = 544;            // bytes per enc e-pair row (136 words)
constexpr int ENC_BUF = 36 * ENC_B;    // 19584

constexpr int OFF_CENT = 0;                          // 4096
constexpr int OFF_MRED = 4096;                       // 64
constexpr int OFF_ZBUF = 4160;                       // 1024 (2*128 partial Z)
constexpr int OFF_WP   = 5184;                       // 216*528 = 114048
constexpr int OFF_A    = OFF_WP + NOUT * ROW_B;      // 119232 (single A tile, 67584)
constexpr int OFF_ENC  = OFF_A + TILE_M * ROW_B;     // 186816 (x2 buffers)
constexpr int OFF_INVZ = OFF_ENC + 2 * ENC_BUF;      // 225984 (2*128 floats)
constexpr int OFF_RACC = OFF_INVZ + 1024;            // 227008 (2*512 floats)
constexpr int SMEM_BYTES = OFF_RACC + 4096;          // 231104

constexpr float LOG2E = 1.4426950408889634f;

__device__ __forceinline__ uint32_t s2u(const void* p) {
    uint32_t a;
    asm("{ .reg .u64 t; cvta.to.shared.u64 t, %1; cvt.u32.u64 %0, t; }"
        : "=r"(a) : "l"(p));
    return a;
}
__device__ __forceinline__ void ldsm4(uint32_t* r, uint32_t addr) {
    asm volatile("ldmatrix.sync.aligned.m8n8.x4.shared.b16 {%0,%1,%2,%3}, [%4];"
                 : "=r"(r[0]), "=r"(r[1]), "=r"(r[2]), "=r"(r[3]) : "r"(addr));
}
__device__ __forceinline__ void ldsm2(uint32_t* r, uint32_t addr) {
    asm volatile("ldmatrix.sync.aligned.m8n8.x2.shared.b16 {%0,%1}, [%2];"
                 : "=r"(r[0]), "=r"(r[1]) : "r"(addr));
}
__device__ __forceinline__ void lds128(uint32_t& r0, uint32_t& r1,
                                       uint32_t& r2, uint32_t& r3, uint32_t addr) {
    asm volatile("ld.shared.v4.b32 {%0,%1,%2,%3}, [%4];"
                 : "=r"(r0), "=r"(r1), "=r"(r2), "=r"(r3) : "r"(addr));
}
__device__ __forceinline__ void hmma(float& d0, float& d1, float& d2, float& d3,
                                     const uint32_t* a, const uint32_t* b) {
    asm volatile("mma.sync.aligned.m16n8k16.row.col.f32.f16.f16.f32 "
                 "{%0,%1,%2,%3}, {%4,%5,%6,%7}, {%8,%9}, {%0,%1,%2,%3};"
                 : "+f"(d0), "+f"(d1), "+f"(d2), "+f"(d3)
                 : "r"(a[0]), "r"(a[1]), "r"(a[2]), "r"(a[3]), "r"(b[0]), "r"(b[1]));
}
__device__ __forceinline__ void fold2(float& acc, float d0, float d1, uint32_t h2raw) {
    __half2 h = *reinterpret_cast<__half2*>(&h2raw);
    float2 e = __half22float2(h);
    acc = fmaf(d0, e.x, fmaf(d1, e.y, acc));
}

// One 8-col strip: 4 ldsm2 B frags (k-quarter = 4 ksteps), 16 HMMAs as two
// m-tile pairs (d[8] live), 2 bulk LDS.128 enc folds for 8 row-groups.
__device__ __forceinline__ void gemm_strip(
    uint32_t bstrip, const uint32_t (&a)[4][4][4], int eo,
    uint32_t eb, float (&acc)[8])
{
    uint32_t b[4][2];
#pragma unroll
    for (int kk = 0; kk < 4; ++kk) ldsm2(b[kk], bstrip + kk * 32);

    const uint32_t ea = eb + (uint32_t)(eo >> 1) * ENC_B;
    uint32_t r0, r1, r2, r3;
    float d[8];

#pragma unroll
    for (int i = 0; i < 8; ++i) d[i] = 0.f;
#pragma unroll
    for (int kk = 0; kk < 4; ++kk) {
        hmma(d[0], d[1], d[2], d[3], a[0][kk], b[kk]);
        hmma(d[4], d[5], d[6], d[7], a[1][kk], b[kk]);
    }
    lds128(r0, r1, r2, r3, ea);
    fold2(acc[0], d[0], d[1], r0);
    fold2(acc[1], d[2], d[3], r1);
    fold2(acc[2], d[4], d[5], r2);
    fold2(acc[3], d[6], d[7], r3);

#pragma unroll
    for (int i = 0; i < 8; ++i) d[i] = 0.f;
#pragma unroll
    for (int kk = 0; kk < 4; ++kk) {
        hmma(d[0], d[1], d[2], d[3], a[2][kk], b[kk]);
        hmma(d[4], d[5], d[6], d[7], a[3][kk], b[kk]);
    }
    lds128(r0, r1, r2, r3, ea + 128);
    fold2(acc[4], d[0], d[1], r0);
    fold2(acc[5], d[2], d[3], r1);
    fold2(acc[6], d[4], d[5], r2);
    fold2(acc[7], d[6], d[7], r3);
}

__device__ __forceinline__ void flush_acc(float (&acc)[8], float* raccp,
                                          int mw, int lq, int l, int col)
{
#pragma unroll
    for (int g = 0; g < 8; ++g) {
        float v = acc[g];
        v += __shfl_xor_sync(0xffffffffu, v, 1);
        v += __shfl_xor_sync(0xffffffffu, v, 2);
        if ((l & 3) == 0)
            atomicAdd(&raccp[(mw * 64 + g * 8 + lq) * 4 + col], v);
        acc[g] = 0.f;
    }
}

__device__ __forceinline__ void load_afrags(uint32_t (&a)[4][4][4],
                                            uint32_t sb, int mw, int kh, int l)
{
    const uint32_t a_base = sb + OFF_A
        + (uint32_t)((mw * 64 + (l & 15)) * ROW_B + kh * 128 + (l >> 4) * 16);
#pragma unroll
    for (int mt = 0; mt < 4; ++mt)
#pragma unroll
        for (int kk = 0; kk < 4; ++kk)
            ldsm4(a[mt][kk], a_base + mt * 16 * ROW_B + kk * 32);
}

// Producer: enc (3 dims) + softmax half (128 clusters, broadcast centroid loads)
// + A-pack (STS.128) + partial-Z combine for one tile.
__device__ __forceinline__ void produce(
    char* smem, const float* __restrict__ X, float Mn,
    int t, int N, int pt, int q, int gp, int buf)
{
    const float4* c4 = reinterpret_cast<const float4*>(smem + OFF_CENT);
    __half2* encp = reinterpret_cast<__half2*>(smem + OFF_ENC + buf * ENC_BUF);
    float* zbuf = reinterpret_cast<float*>(smem + OFF_ZBUF);
    float* invZ = reinterpret_cast<float*>(smem + OFF_INVZ);

    const int p = t * TILE_M + pt;
    float x0 = 0.f, x1 = 0.f, x2 = 0.f;
    if (p < N) { x0 = X[p * 6 + 0]; x1 = X[p * 6 + 1]; x2 = X[p * 6 + 2]; }

    // enc: this thread's 3 dims (q=0: 0-2, q=1: 3-5), streamed double-angle
#pragma unroll
    for (int dd = 0; dd < 3; ++dd) {
        const int d = q * 3 + dd;
        float xv = (p < N) ? X[p * 6 + d] : 0.f;
        float s, c;
        __sincosf(xv, &s, &c);
#pragma unroll
        for (int tt = 0; tt < 3; ++tt) {
            float s1 = 2.f * s * c;
            float c1 = fmaf(-2.f * s, s, 1.f);
            encp[(d * 6 + tt) * 136 + gp]     = __floats2half2_rn(s, s1);
            encp[(d * 6 + 3 + tt) * 136 + gp] = __floats2half2_rn(c, c1);
            s = 2.f * s1 * c1;
            c = fmaf(-2.f * s1, s1, 1.f);
        }
    }

    // scores for this thread's 128-cluster half; all lanes share addresses
    // (broadcast LDS). Pack 8 weights per STS.128 (conflict-free wavefronts).
    const float ub = sqrtf(fmaf(x0, x0, fmaf(x1, x1, x2 * x2))) * Mn;
    const float4* cb = c4 + q * 128;
    uint4* arow = reinterpret_cast<uint4*>(smem + OFF_A + pt * ROW_B + q * 256);
    float z = 0.f;
#pragma unroll 2
    for (int it = 0; it < 16; ++it) {
        uint32_t h[4];
#pragma unroll
        for (int j = 0; j < 4; ++j) {
            float4 ca = cb[it * 8 + 2 * j];
            float4 cd = cb[it * 8 + 2 * j + 1];
            float s0 = fmaf(x0, ca.x, fmaf(x1, ca.y, x2 * ca.z)) - ub;
            float s1 = fmaf(x0, cd.x, fmaf(x1, cd.y, x2 * cd.z)) - ub;
            float w0, w1;
            asm("ex2.approx.ftz.f32 %0, %1;" : "=f"(w0) : "f"(s0));
            asm("ex2.approx.ftz.f32 %0, %1;" : "=f"(w1) : "f"(s1));
            __half2 h2 = __floats2half2_rn(w0, w1);
            z += __low2float(h2) + __high2float(h2);   // Z from rounded weights
            h[j] = *reinterpret_cast<uint32_t*>(&h2);
        }
        arow[it] = make_uint4(h[0], h[1], h[2], h[3]);
    }
    zbuf[q * 128 + pt] = z;
    asm volatile("bar.sync 4, 256;" ::: "memory");   // producer-only barrier
    if (q == 0)
        invZ[buf * 128 + pt] = __frcp_rn(zbuf[pt] + zbuf[128 + pt]);
}

__global__ __launch_bounds__(TPB, 1)
void rgb_hmma_kernel(const float* __restrict__ X,
                     const float* __restrict__ W,
                     const float* __restrict__ cent,
                     float* __restrict__ out, int N, int n_tiles)
{
    extern __shared__ char smem[];
    const uint32_t sb = s2u(smem);
    float4* c4  = reinterpret_cast<float4*>(smem + OFF_CENT);
    float* mred = reinterpret_cast<float*>(smem + OFF_MRED);
    __half* wp  = reinterpret_cast<__half*>(smem + OFF_WP);
    float* invZ = reinterpret_cast<float*>(smem + OFF_INVZ);
    float* racc = reinterpret_cast<float*>(smem + OFF_RACC);

    const int tid = threadIdx.x;
    const int w = tid >> 5, l = tid & 31;

    // ---- init: scaled centroids, W' fp16 transpose, zero racc ----
    for (int i = tid; i < NC; i += TPB) {
        float4 qv;
        qv.x = cent[i * 3 + 0] * LOG2E;
        qv.y = cent[i * 3 + 1] * LOG2E;
        qv.z = cent[i * 3 + 2] * LOG2E;
        qv.w = 0.f;
        c4[i] = qv;
    }
    for (int i = tid; i < 768 * EDIM; i += TPB) {
        int r = i / EDIM, e = i - r * EDIM;
        int c = r / 3, d = r - 3 * c;
        wp[(d * EDIM + e) * (ROW_B / 2) + c] = __float2half_rn(W[i]);
    }
    racc[tid] = 0.f;
    racc[tid + 512] = 0.f;
    __syncthreads();

    float mn2 = 0.f;
    if (tid < NC) {
        float4 cc = c4[tid];
        mn2 = fmaf(cc.x, cc.x, fmaf(cc.y, cc.y, cc.z * cc.z));
    }
#pragma unroll
    for (int o = 16; o > 0; o >>= 1)
        mn2 = fmaxf(mn2, __shfl_xor_sync(0xffffffffu, mn2, o));
    if (l == 0) mred[w] = mn2;
    __syncthreads();
    float M2 = mred[0];
#pragma unroll
    for (int i = 1; i < 16; ++i) M2 = fmaxf(M2, mred[i]);
    const float Mn = sqrtf(M2);

    const bool is_prod = w >= 8;
    // consumer ids (warps 0-7): 2 m-halves x 4 k-quarters, full n
    const int mw = w & 1, kh = (w >> 1) & 3, lq = l >> 2;
    // producer ids (warps 8-15): 2 threads per point (cluster halves)
    const int pp = tid - 256;
    const int pt = pp & 127, q = pp >> 7;
    const int gp = (pt >> 5) * 32 + (pt & 7) * 4 + ((pt >> 3) & 3);

    const uint32_t bl2 = sb + OFF_WP
        + (uint32_t)((l & 7) * ROW_B + ((l >> 3) & 1) * 16 + kh * 128);
    const uint32_t eb0 = sb + OFF_ENC
        + (uint32_t)((l & 3) * ENC_B + mw * 256 + lq * 16);

    const int G = gridDim.x;
    const int bid = blockIdx.x;
    const int nw = (bid < n_tiles) ? ((n_tiles - 1 - bid) / G + 1) : 0;

    // ---- prologue: producers pack tile bid into buffer 0 ----
    if (is_prod && bid < n_tiles)
        produce(smem, X, Mn, bid, N, pt, q, gp, 0);
    __syncthreads();

    uint32_t a[4][4][4];
    int i = 0;
    for (int t = bid; t < n_tiles; t += G, ++i) {
        const int buf = i & 1;
        if (!is_prod) {
            // consume tile t: A-frags from the shared A tile, then release it
            load_afrags(a, sb, mw, kh, l);
            asm volatile("bar.arrive 3, 512;" ::: "memory");

            const uint32_t eb = eb0 + (uint32_t)buf * ENC_BUF;
            float* raccp = racc + buf * 512;
            float acc[8];
#pragma unroll
            for (int g = 0; g < 8; ++g) acc[g] = 0.f;
#pragma unroll
            for (int s = 0; s < 9; ++s)
                gemm_strip(bl2 + (uint32_t)(s * 8 * ROW_B), a, s * 8, eb, acc);
            flush_acc(acc, raccp, mw, lq, l, 0);
#pragma unroll
            for (int s = 9; s < 18; ++s)
                gemm_strip(bl2 + (uint32_t)(s * 8 * ROW_B), a, s * 8 - 72, eb, acc);
            flush_acc(acc, raccp, mw, lq, l, 1);
#pragma unroll
            for (int s = 18; s < 27; ++s)
                gemm_strip(bl2 + (uint32_t)(s * 8 * ROW_B), a, s * 8 - 144, eb, acc);
            flush_acc(acc, raccp, mw, lq, l, 2);
        } else {
            // write out tile t-G (results + invZ from the previous window)
            if (i > 0 && q == 0) {
                float* rp = racc + (buf ^ 1) * 512 + pt * 4;
                const int po = (t - G) * TILE_M + pt;
                if (po < N) {
                    const float iz = invZ[(buf ^ 1) * 128 + pt];
                    out[po * 3 + 0] = rp[0] * iz;
                    out[po * 3 + 1] = rp[1] * iz;
                    out[po * 3 + 2] = rp[2] * iz;
                }
                rp[0] = 0.f; rp[1] = 0.f; rp[2] = 0.f; rp[3] = 0.f;
            }
            // wait until consumers finished reading the A tile
            asm volatile("bar.sync 3, 512;" ::: "memory");
            if (t + G < n_tiles)
                produce(smem, X, Mn, t + G, N, pt, q, gp, buf ^ 1);
        }
        __syncthreads();
    }

    // ---- epilogue: out for the last tile ----
    if (is_prod && q == 0 && nw > 0) {
        const int bufl = (nw - 1) & 1;
        const int tl = bid + (nw - 1) * G;
        const int po = tl * TILE_M + pt;
        if (po < N) {
            const float iz = invZ[bufl * 128 + pt];
            float* rp = racc + bufl * 512 + pt * 4;
            out[po * 3 + 0] = rp[0] * iz;
            out[po * 3 + 1] = rp[1] * iz;
            out[po * 3 + 2] = rp[2] * iz;
        }
    }
}

extern "C" void kernel_launch(void* const* d_in, const int* in_sizes, int n_in,
                              void* d_out, int out_size)
{
    const float* X    = (const float*)d_in[0];  // [N, 6]
    const float* W    = (const float*)d_in[1];  // [768, 72]
    const float* cent = (const float*)d_in[2];  // [256, 3]
    float* out = (float*)d_out;                 // [N, 3]

    const int N = in_sizes[0] / 6;
    const int n_tiles = (N + TILE_M - 1) / TILE_M;

    int dev = 0, sms = 148;
    cudaGetDevice(&dev);
    cudaDeviceGetAttribute(&sms, cudaDevAttrMultiProcessorCount, dev);

    cudaFuncSetAttribute(rgb_hmma_kernel,
                         cudaFuncAttributeMaxDynamicSharedMemorySize, SMEM_BYTES);

    const int grid = n_tiles < sms ? n_tiles : sms;
    rgb_hmma_kernel<<<grid, TPB, SMEM_BYTES>>>(X, W, cent, out, N, n_tiles);
}

// round 15
// speedup vs baseline: 1.6406x; 1.0027x over previous
#include <cuda_runtime.h>
#include <cuda_fp16.h>
#include <stdint.h>

// rgb[n,d] = (1/Z_n) * sum_e enc[n,e] * D[n, d*72+e]
// D = A @ W',  A[n,c] = exp2(s'_nc - ub_n),  s' = x[:3].(centroid*log2e),
// ub_n = |x[:3]| * max_c |centroid'_c|
// WARP-SPECIALIZED: warps 8-15 produce (softmax/enc/pack t+1, out t-1),
// warps 0-7 consume (HMMA GEMM tile t). R14/R15: consumer strip loop is
// register-software-pipelined (B double-buffer + enc prefetch).
// (Resubmission of R14 — previous bench failed at context init: infra transient.)

constexpr int TPB    = 512;
constexpr int TILE_M = 128;
constexpr int NC     = 256;
constexpr int EDIM   = 72;
constexpr int NOUT   = 216;

constexpr int ROW_B  = 528;            // A/W' smem row bytes (132 words)
constexpr int ENC_B  = 544;            // bytes per enc e-pair row (136 words)
constexpr int ENC_BUF = 36 * ENC_B;    // 19584

constexpr int OFF_CENT = 0;                          // 4096
constexpr int OFF_MRED = 4096;                       // 64
constexpr int OFF_ZBUF = 4160;                       // 1024
constexpr int OFF_WP   = 5184;                       // 216*528 = 114048
constexpr int OFF_A    = OFF_WP + NOUT * ROW_B;      // 119232 (single A tile)
constexpr int OFF_ENC  = OFF_A + TILE_M * ROW_B;     // 186816 (x2 buffers)
constexpr int OFF_INVZ = OFF_ENC + 2 * ENC_BUF;      // 225984 (2*128 floats)
constexpr int OFF_RACC = OFF_INVZ + 1024;            // 227008 (2*512 floats)
constexpr int SMEM_BYTES = OFF_RACC + 4096;          // 231104

constexpr float LOG2E = 1.4426950408889634f;

__device__ __forceinline__ uint32_t s2u(const void* p) {
    uint32_t a;
    asm("{ .reg .u64 t; cvta.to.shared.u64 t, %1; cvt.u32.u64 %0, t; }"
        : "=r"(a) : "l"(p));
    return a;
}
__device__ __forceinline__ void ldsm4(uint32_t* r, uint32_t addr) {
    asm volatile("ldmatrix.sync.aligned.m8n8.x4.shared.b16 {%0,%1,%2,%3}, [%4];"
                 : "=r"(r[0]), "=r"(r[1]), "=r"(r[2]), "=r"(r[3]) : "r"(addr));
}
__device__ __forceinline__ void ldsm2(uint32_t* r, uint32_t addr) {
    asm volatile("ldmatrix.sync.aligned.m8n8.x2.shared.b16 {%0,%1}, [%2];"
                 : "=r"(r[0]), "=r"(r[1]) : "r"(addr));
}
__device__ __forceinline__ void lds128(uint32_t& r0, uint32_t& r1,
                                       uint32_t& r2, uint32_t& r3, uint32_t addr) {
    asm volatile("ld.shared.v4.b32 {%0,%1,%2,%3}, [%4];"
                 : "=r"(r0), "=r"(r1), "=r"(r2), "=r"(r3) : "r"(addr));
}
__device__ __forceinline__ void hmma(float& d0, float& d1, float& d2, float& d3,
                                     const uint32_t* a, const uint32_t* b) {
    asm volatile("mma.sync.aligned.m16n8k16.row.col.f32.f16.f16.f32 "
                 "{%0,%1,%2,%3}, {%4,%5,%6,%7}, {%8,%9}, {%0,%1,%2,%3};"
                 : "+f"(d0), "+f"(d1), "+f"(d2), "+f"(d3)
                 : "r"(a[0]), "r"(a[1]), "r"(a[2]), "r"(a[3]), "r"(b[0]), "r"(b[1]));
}
__device__ __forceinline__ void fold2(float& acc, float d0, float d1, uint32_t h2raw) {
    __half2 h = *reinterpret_cast<__half2*>(&h2raw);
    float2 e = __half22float2(h);
    acc = fmaf(d0, e.x, fmaf(d1, e.y, acc));
}

__device__ __forceinline__ void load_b(uint32_t (&b)[4][2], uint32_t bstrip) {
#pragma unroll
    for (int kk = 0; kk < 4; ++kk) ldsm2(b[kk], bstrip + kk * 32);
}

// One 8-col strip with preloaded B frags; enc lds128 issued before the HMMA
// chains so LDS latency hides under tensor work.
__device__ __forceinline__ void gemm_strip_pre(
    const uint32_t (&b)[4][2], const uint32_t (&a)[4][4][4], int eo,
    uint32_t eb, float (&acc)[8])
{
    const uint32_t ea = eb + (uint32_t)(eo >> 1) * ENC_B;
    uint32_t e0, e1, e2, e3, e4, e5, e6, e7;
    lds128(e0, e1, e2, e3, ea);
    lds128(e4, e5, e6, e7, ea + 128);

    float d[8];
#pragma unroll
    for (int i = 0; i < 8; ++i) d[i] = 0.f;
#pragma unroll
    for (int kk = 0; kk < 4; ++kk) {
        hmma(d[0], d[1], d[2], d[3], a[0][kk], b[kk]);
        hmma(d[4], d[5], d[6], d[7], a[1][kk], b[kk]);
    }
    fold2(acc[0], d[0], d[1], e0);
    fold2(acc[1], d[2], d[3], e1);
    fold2(acc[2], d[4], d[5], e2);
    fold2(acc[3], d[6], d[7], e3);

#pragma unroll
    for (int i = 0; i < 8; ++i) d[i] = 0.f;
#pragma unroll
    for (int kk = 0; kk < 4; ++kk) {
        hmma(d[0], d[1], d[2], d[3], a[2][kk], b[kk]);
        hmma(d[4], d[5], d[6], d[7], a[3][kk], b[kk]);
    }
    fold2(acc[4], d[0], d[1], e4);
    fold2(acc[5], d[2], d[3], e5);
    fold2(acc[6], d[4], d[5], e6);
    fold2(acc[7], d[6], d[7], e7);
}

__device__ __forceinline__ void flush_acc(float (&acc)[8], float* raccp,
                                          int mw, int lq, int l, int col)
{
#pragma unroll
    for (int g = 0; g < 8; ++g) {
        float v = acc[g];
        v += __shfl_xor_sync(0xffffffffu, v, 1);
        v += __shfl_xor_sync(0xffffffffu, v, 2);
        if ((l & 3) == 0)
            atomicAdd(&raccp[(mw * 64 + g * 8 + lq) * 4 + col], v);
        acc[g] = 0.f;
    }
}

__device__ __forceinline__ void load_afrags(uint32_t (&a)[4][4][4],
                                            uint32_t sb, int mw, int kh, int l)
{
    const uint32_t a_base = sb + OFF_A
        + (uint32_t)((mw * 64 + (l & 15)) * ROW_B + kh * 128 + (l >> 4) * 16);
#pragma unroll
    for (int mt = 0; mt < 4; ++mt)
#pragma unroll
        for (int kk = 0; kk < 4; ++kk)
            ldsm4(a[mt][kk], a_base + mt * 16 * ROW_B + kk * 32);
}

// Producer: enc (3 dims) + softmax half (broadcast centroid loads) +
// A-pack (STS.128) + partial-Z combine.
__device__ __forceinline__ void produce(
    char* smem, const float* __restrict__ X, float Mn,
    int t, int N, int pt, int q, int gp, int buf)
{
    const float4* c4 = reinterpret_cast<const float4*>(smem + OFF_CENT);
    __half2* encp = reinterpret_cast<__half2*>(smem + OFF_ENC + buf * ENC_BUF);
    float* zbuf = reinterpret_cast<float*>(smem + OFF_ZBUF);
    float* invZ = reinterpret_cast<float*>(smem + OFF_INVZ);

    const int p = t * TILE_M + pt;
    float x0 = 0.f, x1 = 0.f, x2 = 0.f;
    if (p < N) { x0 = X[p * 6 + 0]; x1 = X[p * 6 + 1]; x2 = X[p * 6 + 2]; }

#pragma unroll
    for (int dd = 0; dd < 3; ++dd) {
        const int d = q * 3 + dd;
        float xv = (p < N) ? X[p * 6 + d] : 0.f;
        float s, c;
        __sincosf(xv, &s, &c);
#pragma unroll
        for (int tt = 0; tt < 3; ++tt) {
            float s1 = 2.f * s * c;
            float c1 = fmaf(-2.f * s, s, 1.f);
            encp[(d * 6 + tt) * 136 + gp]     = __floats2half2_rn(s, s1);
            encp[(d * 6 + 3 + tt) * 136 + gp] = __floats2half2_rn(c, c1);
            s = 2.f * s1 * c1;
            c = fmaf(-2.f * s1, s1, 1.f);
        }
    }

    const float ub = sqrtf(fmaf(x0, x0, fmaf(x1, x1, x2 * x2))) * Mn;
    const float4* cb = c4 + q * 128;
    uint4* arow = reinterpret_cast<uint4*>(smem + OFF_A + pt * ROW_B + q * 256);
    float z = 0.f;
#pragma unroll 2
    for (int it = 0; it < 16; ++it) {
        uint32_t h[4];
#pragma unroll
        for (int j = 0; j < 4; ++j) {
            float4 ca = cb[it * 8 + 2 * j];
            float4 cd = cb[it * 8 + 2 * j + 1];
            float s0 = fmaf(x0, ca.x, fmaf(x1, ca.y, x2 * ca.z)) - ub;
            float s1 = fmaf(x0, cd.x, fmaf(x1, cd.y, x2 * cd.z)) - ub;
            float w0, w1;
            asm("ex2.approx.ftz.f32 %0, %1;" : "=f"(w0) : "f"(s0));
            asm("ex2.approx.ftz.f32 %0, %1;" : "=f"(w1) : "f"(s1));
            __half2 h2 = __floats2half2_rn(w0, w1);
            z += __low2float(h2) + __high2float(h2);
            h[j] = *reinterpret_cast<uint32_t*>(&h2);
        }
        arow[it] = make_uint4(h[0], h[1], h[2], h[3]);
    }
    zbuf[q * 128 + pt] = z;
    asm volatile("bar.sync 4, 256;" ::: "memory");   // producer-only barrier
    if (q == 0)
        invZ[buf * 128 + pt] = __frcp_rn(zbuf[pt] + zbuf[128 + pt]);
}

__global__ __launch_bounds__(TPB, 1)
void rgb_hmma_kernel(const float* __restrict__ X,
                     const float* __restrict__ W,
                     const float* __restrict__ cent,
                     float* __restrict__ out, int N, int n_tiles)
{
    extern __shared__ char smem[];
    const uint32_t sb = s2u(smem);
    float4* c4  = reinterpret_cast<float4*>(smem + OFF_CENT);
    float* mred = reinterpret_cast<float*>(smem + OFF_MRED);
    __half* wp  = reinterpret_cast<__half*>(smem + OFF_WP);
    float* invZ = reinterpret_cast<float*>(smem + OFF_INVZ);
    float* racc = reinterpret_cast<float*>(smem + OFF_RACC);

    const int tid = threadIdx.x;
    const int w = tid >> 5, l = tid & 31;

    for (int i = tid; i < NC; i += TPB) {
        float4 qv;
        qv.x = cent[i * 3 + 0] * LOG2E;
        qv.y = cent[i * 3 + 1] * LOG2E;
        qv.z = cent[i * 3 + 2] * LOG2E;
        qv.w = 0.f;
        c4[i] = qv;
    }
    for (int i = tid; i < 768 * EDIM; i += TPB) {
        int r = i / EDIM, e = i - r * EDIM;
        int c = r / 3, d = r - 3 * c;
        wp[(d * EDIM + e) * (ROW_B / 2) + c] = __float2half_rn(W[i]);
    }
    racc[tid] = 0.f;
    racc[tid + 512] = 0.f;
    __syncthreads();

    float mn2 = 0.f;
    if (tid < NC) {
        float4 cc = c4[tid];
        mn2 = fmaf(cc.x, cc.x, fmaf(cc.y, cc.y, cc.z * cc.z));
    }
#pragma unroll
    for (int o = 16; o > 0; o >>= 1)
        mn2 = fmaxf(mn2, __shfl_xor_sync(0xffffffffu, mn2, o));
    if (l == 0) mred[w] = mn2;
    __syncthreads();
    float M2 = mred[0];
#pragma unroll
    for (int i = 1; i < 16; ++i) M2 = fmaxf(M2, mred[i]);
    const float Mn = sqrtf(M2);

    const bool is_prod = w >= 8;
    const int mw = w & 1, kh = (w >> 1) & 3, lq = l >> 2;
    const int pp = tid - 256;
    const int pt = pp & 127, q = pp >> 7;
    const int gp = (pt >> 5) * 32 + (pt & 7) * 4 + ((pt >> 3) & 3);

    const uint32_t bl2 = sb + OFF_WP
        + (uint32_t)((l & 7) * ROW_B + ((l >> 3) & 1) * 16 + kh * 128);
    const uint32_t eb0 = sb + OFF_ENC
        + (uint32_t)((l & 3) * ENC_B + mw * 256 + lq * 16);

    const int G = gridDim.x;
    const int bid = blockIdx.x;
    const int nw = (bid < n_tiles) ? ((n_tiles - 1 - bid) / G + 1) : 0;

    if (is_prod && bid < n_tiles)
        produce(smem, X, Mn, bid, N, pt, q, gp, 0);
    __syncthreads();

    uint32_t a[4][4][4];
    int i = 0;
    for (int t = bid; t < n_tiles; t += G, ++i) {
        const int buf = i & 1;
        if (!is_prod) {
            load_afrags(a, sb, mw, kh, l);
            asm volatile("bar.arrive 3, 512;" ::: "memory");

            const uint32_t eb = eb0 + (uint32_t)buf * ENC_BUF;
            float* raccp = racc + buf * 512;
            float acc[8];
#pragma unroll
            for (int g = 0; g < 8; ++g) acc[g] = 0.f;

            // software-pipelined strip sweep: B frags for s+1 load under
            // strip s's HMMAs; enc folds prefetch at strip top.
            uint32_t bcur[4][2], bnxt[4][2];
            load_b(bcur, bl2);
#pragma unroll
            for (int s = 0; s < 27; ++s) {
                if (s < 26)
                    load_b(bnxt, bl2 + (uint32_t)((s + 1) * 8 * ROW_B));
                const int eo = s * 8 - (s >= 9 ? 72 : 0) - (s >= 18 ? 72 : 0);
                gemm_strip_pre(bcur, a, eo, eb, acc);
                if (s == 8)  flush_acc(acc, raccp, mw, lq, l, 0);
                if (s == 17) flush_acc(acc, raccp, mw, lq, l, 1);
                if (s == 26) flush_acc(acc, raccp, mw, lq, l, 2);
#pragma unroll
                for (int kk = 0; kk < 4; ++kk) {
                    bcur[kk][0] = bnxt[kk][0];
                    bcur[kk][1] = bnxt[kk][1];
                }
            }
        } else {
            if (i > 0 && q == 0) {
                float* rp = racc + (buf ^ 1) * 512 + pt * 4;
                const int po = (t - G) * TILE_M + pt;
                if (po < N) {
                    const float iz = invZ[(buf ^ 1) * 128 + pt];
                    out[po * 3 + 0] = rp[0] * iz;
                    out[po * 3 + 1] = rp[1] * iz;
                    out[po * 3 + 2] = rp[2] * iz;
                }
                rp[0] = 0.f; rp[1] = 0.f; rp[2] = 0.f; rp[3] = 0.f;
            }
            asm volatile("bar.sync 3, 512;" ::: "memory");
            if (t + G < n_tiles)
                produce(smem, X, Mn, t + G, N, pt, q, gp, buf ^ 1);
        }
        __syncthreads();
    }

    if (is_prod && q == 0 && nw > 0) {
        const int bufl = (nw - 1) & 1;
        const int tl = bid + (nw - 1) * G;
        const int po = tl * TILE_M + pt;
        if (po < N) {
            const float iz = invZ[bufl * 128 + pt];
            float* rp = racc + bufl * 512 + pt * 4;
            out[po * 3 + 0] = rp[0] * iz;
            out[po * 3 + 1] = rp[1] * iz;
            out[po * 3 + 2] = rp[2] * iz;
        }
    }
}

extern "C" void kernel_launch(void* const* d_in, const int* in_sizes, int n_in,
                              void* d_out, int out_size)
{
    const float* X    = (const float*)d_in[0];  // [N, 6]
    const float* W    = (const float*)d_in[1];  // [768, 72]
    const float* cent = (const float*)d_in[2];  // [256, 3]
    float* out = (float*)d_out;                 // [N, 3]

    const int N = in_sizes[0] / 6;
    const int n_tiles = (N + TILE_M - 1) / TILE_M;

    int dev = 0, sms = 148;
    cudaGetDevice(&dev);
    cudaDeviceGetAttribute(&sms, cudaDevAttrMultiProcessorCount, dev);

    cudaFuncSetAttribute(rgb_hmma_kernel,
                         cudaFuncAttributeMaxDynamicSharedMemorySize, SMEM_BYTES);

    const int grid = n_tiles < sms ? n_tiles : sms;
    rgb_hmma_kernel<<<grid, TPB, SMEM_BYTES>>>(X, W, cent, out, N, n_tiles);
}